// round 15
// baseline (speedup 1.0000x reference)
#include <cuda_runtime.h>
#include <cuda_fp16.h>
#include <mma.h>
using namespace nvcuda;

// ---------------- problem constants ----------------
constexpr int NB   = 256;
constexpr int NT   = 576;
constexpr int NFT  = 24;
constexpr int NM   = 32;
constexpr int NH   = 256;
constexpr int NE   = 512;
constexpr int KX1  = 544;
constexpr int KX2  = 800;
constexpr int G4   = 1024;
constexpr int NC   = NT + NH;   // 832 combined attn1+fc columns
constexpr float EPSC = 1e-6f;

constexpr int BM = 32;
constexpr int KT = 32;
constexpr int SK = KT + 8;   // smem half row stride
constexpr int ST = 4;        // pipeline stages

// offsets
constexpr int sX2B = 2 * NB * KX2;       // stride between X2 ping-pong buffers
constexpr int oWcat = 2 * G4 * KX2;      // lo offset (split weights)
constexpr int oWcomb = NC * KX1;

// ---------------- scratch (device globals) ----------------
__device__ __align__(16) __half g_X1h[NB * KX1];          // plain fp16 activations
__device__ __align__(16) __half g_tmph[NB * NT];
__device__ __align__(16) __half g_X2h[2 * sX2B];          // ping-pong
__device__ __align__(16) __half g_aW2h[NT * NT];          // attn2 weights plain fp16
__device__ __align__(16) __half g_Wcath[2 * 2 * G4 * KX2];
__device__ __align__(16) __half g_Wcombh[2 * NC * KX1];
__device__ __align__(16) unsigned char g_enc8[(long)NB * NT * NE];  // enc fp8 e4m3
__device__ __align__(16) float g_logits[NB * NT];
__device__ __align__(16) float g_alpha[NB * NFT];
__device__ __align__(16) float g_c[2 * NB * NH];
__device__ __align__(16) float g_bias2[2 * G4];
__device__ __align__(16) float g_bcomb[NC];

__device__ __forceinline__ float sigm(float x) { return 1.0f / (1.0f + expf(-x)); }
__device__ __forceinline__ void fsplit(float v, __half& hi, __half& lo) {
    hi = __float2half(v);
    lo = __float2half(v - __half2float(hi));
}
__device__ __forceinline__ void cpa16(void* d, const void* s) {
    unsigned sd = (unsigned)__cvta_generic_to_shared(d);
    asm volatile("cp.async.cg.shared.global [%0], [%1], 16;" :: "r"(sd), "l"(s));
}
__device__ __forceinline__ void cp_commit() { asm volatile("cp.async.commit_group;"); }
template<int N_> __device__ __forceinline__ void cp_wait() {
    asm volatile("cp.async.wait_group %0;" :: "n"(N_));
}
__device__ __forceinline__ unsigned short f2_to_fp8x2(float hi, float lo) {
    unsigned short r;
    asm("cvt.rn.satfinite.e4m3x2.f32 %0, %1, %2;" : "=h"(r) : "f"(hi), "f"(lo));
    return r;
}
__device__ __forceinline__ __half2 fp8x2_to_half2(unsigned short v) {
    unsigned r;
    asm("cvt.rn.f16x2.e4m3x2 %0, %1;" : "=r"(r) : "h"(v));
    return *reinterpret_cast<__half2*>(&r);
}

// ---------------- one-time setup ----------------
__global__ void setup_kernel(const float* __restrict__ hidden, const float* __restrict__ cell,
                             const float* __restrict__ ff, const float* __restrict__ fb2,
                             float* __restrict__ out, float* __restrict__ c,
                             __half* __restrict__ X1, __half* __restrict__ X2)
{
    const int N0 = NB * NFT;
    const int N1 = 2 * NB * NH;
    const int N2 = NB * KX1;
    const int N3 = 2 * NB * 288;
    const int total = N0 + N1 + N2 + N3;
    for (int i = blockIdx.x * blockDim.x + threadIdx.x; i < total; i += gridDim.x * blockDim.x) {
        int r = i;
        if (r < N0) { out[r] = fb2[0]; continue; }
        r -= N0;
        if (r < N1) { c[r] = cell[r]; continue; }
        r -= N1;
        if (r < N2) {
            int b = r / KX1, k = r % KX1;
            float v;
            if (k < 512) v = hidden[(k < 256 ? 0 : 1) * NB * NH + b * NH + (k & 255)];
            else         v = ff[b * NFT * NM + (k - 512)];
            X1[r] = __float2half(v); continue;
        }
        r -= N2;
        int d = r / (NB * 288); int r2 = r % (NB * 288);
        int b = r2 / 288, k = r2 % 288;
        float v = (k < NM) ? ff[b * NFT * NM + k]
                           : hidden[d * NB * NH + b * NH + (k - NM)];
        X2[(d * NB + b) * KX2 + 512 + k] = __float2half(v);
    }
}

// ---------------- alpha (once) ----------------
__global__ void alpha_kernel(const float* __restrict__ ff, const float* __restrict__ fh,
                             float* __restrict__ alpha)
{
    int b = blockIdx.x, tid = threadIdx.x;
    int f = tid / 24, p = tid % 24;
    __shared__ float dist[24][24];
    __shared__ float dp[24];
    const float* x = ff + (b * NFT + f) * NM;
    const float* y = fh + ((long)b * NT + p * 24 + f) * NM;
    float s = 0.0f;
#pragma unroll
    for (int m = 0; m < NM; m++) { float d = x[m] - y[m] + EPSC; s += d * d; }
    dist[f][p] = sqrtf(s);
    __syncthreads();
    if (p == 0) { float t = 0.0f; for (int q = 0; q < 24; q++) t += dist[f][q]; dp[f] = 1.0f / t; }
    __syncthreads();
    if (tid == 0) {
        float mx = -1e30f;
        for (int q = 0; q < 24; q++) mx = fmaxf(mx, dp[q]);
        float e[24]; float ss = 0.0f;
        for (int q = 0; q < 24; q++) { e[q] = expf(dp[q] - mx); ss += e[q]; }
        float inv = 1.0f / ss;
        for (int q = 0; q < 24; q++) alpha[b * 24 + q] = e[q] * inv;
    }
}

// ---------------- pack gate-interleaved [W_ih | W_hh] split + combined bias ----------------
__global__ void wcat_kernel(const float* __restrict__ Wih, const float* __restrict__ Whh,
                            const float* __restrict__ bih, const float* __restrict__ bhh,
                            __half* __restrict__ Wcat, float* __restrict__ bias2)
{
    const int total = 2 * G4 * KX2;
    for (int i = blockIdx.x * blockDim.x + threadIdx.x; i < total; i += gridDim.x * blockDim.x) {
        int d = i / (G4 * KX2); int r = i % (G4 * KX2);
        int np = r / KX2, k = r % KX2;
        int n = (np & 3) * 256 + (np >> 2);
        float v = (k < KX1) ? Wih[(long)(d * G4 + n) * KX1 + k]
                            : Whh[(long)(d * G4 + n) * NH + (k - KX1)];
        __half h, l; fsplit(v, h, l);
        Wcat[i] = h; Wcat[total + i] = l;
    }
    int tid = blockIdx.x * blockDim.x + threadIdx.x;
    if (tid < 2 * G4) {
        int d = tid / G4, np = tid % G4;
        int n = (np & 3) * 256 + (np >> 2);
        bias2[tid] = bih[d * G4 + n] + bhh[d * G4 + n];
    }
}

// ---------------- pack combined [aW1 ; fW1 zero-padded] + bias (once) ----------------
__global__ void wcomb_kernel(const float* __restrict__ aW1, const float* __restrict__ ab1,
                             const float* __restrict__ fW1, const float* __restrict__ fb1,
                             __half* __restrict__ Wc, float* __restrict__ bc)
{
    const int total = NC * KX1;
    for (int i = blockIdx.x * blockDim.x + threadIdx.x; i < total; i += gridDim.x * blockDim.x) {
        int n = i / KX1, k = i % KX1;
        float v;
        if (n < NT) v = aW1[n * KX1 + k];
        else        v = (k < NE) ? fW1[(n - NT) * NE + k] : 0.0f;
        __half h, l; fsplit(v, h, l);
        Wc[i] = h; Wc[total + i] = l;
    }
    int tid = blockIdx.x * blockDim.x + threadIdx.x;
    if (tid < NC) bc[tid] = (tid < NT) ? ab1[tid] : fb1[tid - NT];
}

// ---------------- converters ----------------
__global__ void conv_half(const float* __restrict__ src, __half* __restrict__ dst, int n)
{
    for (int i = blockIdx.x * blockDim.x + threadIdx.x; i < n; i += gridDim.x * blockDim.x)
        dst[i] = __float2half(src[i]);
}

__global__ void conv_fp8(const float4* __restrict__ src, unsigned* __restrict__ dst, int n4)
{
    for (int i = blockIdx.x * blockDim.x + threadIdx.x; i < n4; i += gridDim.x * blockDim.x) {
        float4 v = src[i];
        unsigned short s01 = f2_to_fp8x2(v.y, v.x);
        unsigned short s23 = f2_to_fp8x2(v.w, v.z);
        dst[i] = (unsigned)s01 | ((unsigned)s23 << 16);
    }
}

// ---------------- 4-stage fp16-A x fp16/split-W tensor-core GEMM with PDL ----------------
// NW = 1 (plain W) or 2 (split W hi+lo, independent accumulators).
// PDL: W stages prefetch BEFORE cudaGridDependencySynchronize(); A after.
// EPI: 0 fp32 out (attn2), 2 LSTM cell (BN=64, gate-interleaved),
//      4 combined attn1+fc: cols<NT -> tanh to tmp; cols>=NT -> relu.w2 -> out
template<int BN, int EPI, int NW>
__global__ __launch_bounds__(128) void hgemm2(
    const __half* __restrict__ Ah, const __half* __restrict__ Whi, const __half* __restrict__ Wlo,
    const float* __restrict__ bias, int K, int N,
    long sA, long sW, long sB,
    float* __restrict__ Cf, long sC, __half* __restrict__ Ch,
    float* __restrict__ cst, __half* __restrict__ X1, __half* __restrict__ X2out,
    const float* __restrict__ w2, float* __restrict__ out, int tstep, int yoff)
{
    const long z = blockIdx.z;
    Ah += z * sA; Whi += z * sW; Wlo += z * sW; bias += z * sB;
    extern __shared__ char dsm[];
    __half* As = (__half*)dsm;                         // [ST][BM][SK]
    __half* Ws = As + ST * BM * SK;                    // [ST][NW][BN][SK]
    float*  Cs = (float*)(Ws + ST * NW * BN * SK);     // [BM][BN+4]
    float*  red = Cs + BM * (BN + 4);                  // [128]
    auto ap = [&](int st, int r) { return As + (st * BM + r) * SK; };
    auto wp = [&](int st, int hf, int r) { return Ws + ((st * NW + hf) * BN + r) * SK; };

    const int tid = threadIdx.x;
    const int m0 = blockIdx.x * BM, n0 = (blockIdx.y + yoff) * BN;
    const int warp = tid >> 5, wm = warp >> 1, wn = warp & 1;
    const int ar = tid >> 2, ac = (tid & 3) * 8;
    const int nk = K / KT;

    wmma::fragment<wmma::accumulator, 16, 16, 16, float> acc0[NW], acc1[NW];
#pragma unroll
    for (int q = 0; q < NW; q++) {
        wmma::fill_fragment(acc0[q], 0.0f);
        if (BN == 64) wmma::fill_fragment(acc1[q], 0.0f);
    }

    auto load_w = [&](int st, int kt) {
        const int k0 = kt * KT;
        cpa16(wp(st, 0, ar) + ac, Whi + (long)(n0 + ar) * K + k0 + ac);
        if (NW == 2) cpa16(wp(st, 1, ar) + ac, Wlo + (long)(n0 + ar) * K + k0 + ac);
        if (BM < BN) {
            cpa16(wp(st, 0, ar + BM) + ac, Whi + (long)(n0 + ar + BM) * K + k0 + ac);
            if (NW == 2) cpa16(wp(st, 1, ar + BM) + ac, Wlo + (long)(n0 + ar + BM) * K + k0 + ac);
        }
    };
    auto load_a = [&](int st, int kt) {
        const int k0 = kt * KT;
        cpa16(ap(st, ar) + ac, Ah + (long)(m0 + ar) * K + k0 + ac);
    };

    // PDL prologue: W prefetch independent of predecessor
    load_w(0, 0); cp_commit();
    load_w(1, 1); cp_commit();
    load_w(2, 2); cp_commit();
    cudaGridDependencySynchronize();     // wait for upstream producer of A
    load_a(0, 0); cp_commit();
    load_a(1, 1); cp_commit();
    load_a(2, 2); cp_commit();

    for (int kt = 0; kt < nk; kt++) {
        const int cur = kt % ST;
        if (kt + 3 < nk) {
            const int st = (kt + 3) % ST;
            load_a(st, kt + 3); load_w(st, kt + 3); cp_commit();
            cp_wait<3>();
        } else if (kt + 2 < nk) {
            cp_wait<2>();
        } else if (kt + 1 < nk) {
            cp_wait<1>();
        } else {
            cp_wait<0>();
        }
        __syncthreads();
#pragma unroll
        for (int sub = 0; sub < KT; sub += 16) {
            wmma::fragment<wmma::matrix_a, 16, 16, 16, __half, wmma::row_major> ah;
            wmma::load_matrix_sync(ah, ap(cur, wm * 16) + sub, SK);
            wmma::fragment<wmma::matrix_b, 16, 16, 16, __half, wmma::col_major> bh, bl;
            if (BN == 64) {
                wmma::load_matrix_sync(bh, wp(cur, 0, wn * 32) + sub, SK);
                wmma::mma_sync(acc0[0], ah, bh, acc0[0]);
                if (NW == 2) {
                    wmma::load_matrix_sync(bl, wp(cur, 1, wn * 32) + sub, SK);
                    wmma::mma_sync(acc0[1], ah, bl, acc0[1]);
                }
                wmma::load_matrix_sync(bh, wp(cur, 0, wn * 32 + 16) + sub, SK);
                wmma::mma_sync(acc1[0], ah, bh, acc1[0]);
                if (NW == 2) {
                    wmma::load_matrix_sync(bl, wp(cur, 1, wn * 32 + 16) + sub, SK);
                    wmma::mma_sync(acc1[1], ah, bl, acc1[1]);
                }
            } else {
                wmma::load_matrix_sync(bh, wp(cur, 0, wn * 16) + sub, SK);
                wmma::mma_sync(acc0[0], ah, bh, acc0[0]);
                if (NW == 2) {
                    wmma::load_matrix_sync(bl, wp(cur, 1, wn * 16) + sub, SK);
                    wmma::mma_sync(acc0[1], ah, bl, acc0[1]);
                }
            }
        }
        __syncthreads();
    }

    cudaTriggerProgrammaticLaunchCompletion();   // successor may start W prefetch

    if (NW == 2) {
#pragma unroll
        for (int e = 0; e < acc0[0].num_elements; e++) {
            acc0[0].x[e] += acc0[1].x[e];
            if (BN == 64) acc1[0].x[e] += acc1[1].x[e];
        }
    }
    if (BN == 64) {
        wmma::store_matrix_sync(Cs + (wm * 16) * (BN + 4) + wn * 32, acc0[0], BN + 4, wmma::mem_row_major);
        wmma::store_matrix_sync(Cs + (wm * 16) * (BN + 4) + wn * 32 + 16, acc1[0], BN + 4, wmma::mem_row_major);
    } else {
        wmma::store_matrix_sync(Cs + (wm * 16) * (BN + 4) + wn * 16, acc0[0], BN + 4, wmma::mem_row_major);
    }
    __syncthreads();

    if (EPI == 0) {
        for (int idx = tid; idx < BM * BN; idx += 128) {
            int m = idx / BN, n = idx % BN;
            Cf[(long)(m0 + m) * N + n0 + n + z * sC] = Cs[m * (BN + 4) + n] + bias[n0 + n];
        }
    } else if (EPI == 2) {
        const int d = (int)z;
        for (int idx = tid; idx < BM * 16; idx += 128) {
            int m = idx >> 4, jj = idx & 15;
            int b = m0 + m, j = (n0 >> 2) + jj;
            float ig = sigm(Cs[m * (BN + 4) + jj * 4 + 0] + bias[n0 + jj * 4 + 0]);
            float fg = sigm(Cs[m * (BN + 4) + jj * 4 + 1] + bias[n0 + jj * 4 + 1]);
            float gg = tanhf(Cs[m * (BN + 4) + jj * 4 + 2] + bias[n0 + jj * 4 + 2]);
            float og = sigm(Cs[m * (BN + 4) + jj * 4 + 3] + bias[n0 + jj * 4 + 3]);
            int ci = (d * NB + b) * NH + j;
            float cn = fg * cst[ci] + ig * gg;
            float hn = og * tanhf(cn);
            cst[ci] = cn;
            __half h = __float2half(hn);
            X2out[(d * NB + b) * KX2 + 544 + j] = h;   // into NEXT X2 buffer
            X1[b * KX1 + d * NH + j] = h;              // into X1 (hh slice)
        }
    } else {  // EPI == 4, BN == 32: combined attn1 + fc
        if (n0 < NT) {
            for (int idx = tid; idx < BM * BN; idx += 128) {
                int m = idx / BN, n = idx % BN;
                float v = tanhf(Cs[m * (BN + 4) + n] + bias[n0 + n]);
                Ch[(long)(m0 + m) * NT + n0 + n] = __float2half(v);
            }
        } else if (tstep >= 0) {
            int r = tid >> 2, g = tid & 3;
            float s = 0.0f;
#pragma unroll
            for (int jj = 0; jj < 8; jj++) {
                int n = g * 8 + jj;
                float v = fmaxf(Cs[r * (BN + 4) + n] + bias[n0 + n], 0.0f);
                s += v * w2[n0 - NT + n];
            }
            red[tid] = s;
            __syncthreads();
            if (tid < 32) {
                float t = red[tid * 4] + red[tid * 4 + 1] + red[tid * 4 + 2] + red[tid * 4 + 3];
                atomicAdd(&out[(m0 + tid) * NFT + tstep], t);
            }
        }
    }
}

constexpr int smem_sz(int bn, int nw) {
    return (ST * BM * SK + ST * nw * bn * SK) * 2 + BM * (bn + 4) * 4 + 128 * 4 + 256;
}
constexpr int SMEM32_2 = smem_sz(32, 2);
constexpr int SMEM32_1 = smem_sz(32, 1);
constexpr int SMEM64_2 = smem_sz(64, 2);

// ---------------- ctx: one block per batch row; softmax once; fp8 enc stream; PDL ----------------
__global__ __launch_bounds__(128) void ctx_kernel(
    const float* __restrict__ logits, const float* __restrict__ alpha,
    const unsigned char* __restrict__ enc8, __half* __restrict__ X2h, __half* __restrict__ X1h,
    const float* __restrict__ ffC, const float* __restrict__ ffN)
{
    const int b = blockIdx.x;
    const int tid = threadIdx.x;
    __shared__ float wt[NT];
    __shared__ float sred[4];
    const float* lrow = logits + b * NT;

    cudaGridDependencySynchronize();   // logits must be complete

    float mx = -1e30f;
    for (int t = tid; t < NT; t += 128) mx = fmaxf(mx, lrow[t]);
#pragma unroll
    for (int o = 16; o > 0; o >>= 1) mx = fmaxf(mx, __shfl_xor_sync(0xffffffffu, mx, o));
    if ((tid & 31) == 0) sred[tid >> 5] = mx;
    __syncthreads();
    mx = fmaxf(fmaxf(sred[0], sred[1]), fmaxf(sred[2], sred[3]));
    __syncthreads();

    float s = 0.0f;
    for (int t = tid; t < NT; t += 128) { float e = expf(lrow[t] - mx); wt[t] = e; s += e; }
#pragma unroll
    for (int o = 16; o > 0; o >>= 1) s += __shfl_xor_sync(0xffffffffu, s, o);
    if ((tid & 31) == 0) sred[tid >> 5] = s;
    __syncthreads();
    s = sred[0] + sred[1] + sred[2] + sred[3];
    float inv = 1.0f / s;
    for (int t = tid; t < NT; t += 128) wt[t] *= inv * alpha[b * 24 + t / 24];
    __syncthreads();

    cudaTriggerProgrammaticLaunchCompletion();   // gates W-prefetch overlaps enc stream

    // 4 columns per thread (128 thr x 4 = 512 cols), fp8 packed as uint
    const unsigned* eb = (const unsigned*)(enc8 + (long)b * NT * NE) + tid;
    float a0 = 0, a1 = 0, a2 = 0, a3 = 0;
#pragma unroll 1
    for (int t = 0; t < NT; t += 8) {
        unsigned q0 = eb[(t + 0) * 128];
        unsigned q1 = eb[(t + 1) * 128];
        unsigned q2 = eb[(t + 2) * 128];
        unsigned q3 = eb[(t + 3) * 128];
        unsigned q4 = eb[(t + 4) * 128];
        unsigned q5 = eb[(t + 5) * 128];
        unsigned q6 = eb[(t + 6) * 128];
        unsigned q7 = eb[(t + 7) * 128];
#pragma unroll
        for (int i = 0; i < 8; i++) {
            unsigned q = (i == 0) ? q0 : (i == 1) ? q1 : (i == 2) ? q2 : (i == 3) ? q3
                       : (i == 4) ? q4 : (i == 5) ? q5 : (i == 6) ? q6 : q7;
            float w = wt[t + i];
            float2 f01 = __half22float2(fp8x2_to_half2((unsigned short)(q & 0xffff)));
            float2 f23 = __half22float2(fp8x2_to_half2((unsigned short)(q >> 16)));
            a0 += w * f01.x; a1 += w * f01.y; a2 += w * f23.x; a3 += w * f23.y;
        }
    }
    __half2 p01 = __floats2half2_rn(a0, a1);
    __half2 p23 = __floats2half2_rn(a2, a3);
    long o0 = (long)b * KX2 + 4 * tid;
    long o1 = (long)(NB + b) * KX2 + 4 * tid;
    *(__half2*)(X2h + o0) = p01; *(__half2*)(X2h + o0 + 2) = p23;
    *(__half2*)(X2h + o1) = p01; *(__half2*)(X2h + o1 + 2) = p23;

    if (tid < NM) {
        __half h = __float2half(ffC[b * NFT * NM + tid]);
        X2h[(long)b * KX2 + 512 + tid] = h;
        X2h[(long)(NB + b) * KX2 + 512 + tid] = h;
        if (ffN != nullptr)
            X1h[b * KX1 + 512 + tid] = __float2half(ffN[b * NFT * NM + tid]);
    }
}

// ---------------- PDL launch helper ----------------
template<typename F, typename... Args>
static void launch_pdl(F* k, dim3 grid, dim3 block, size_t smem, Args... args)
{
    cudaLaunchConfig_t cfg = {};
    cfg.gridDim = grid; cfg.blockDim = block; cfg.dynamicSmemBytes = smem; cfg.stream = 0;
    cudaLaunchAttribute at[1];
    at[0].id = cudaLaunchAttributeProgrammaticStreamSerialization;
    at[0].val.programmaticStreamSerializationAllowed = 1;
    cfg.attrs = at; cfg.numAttrs = 1;
    cudaLaunchKernelEx(&cfg, k, args...);
}

// ---------------- launch ----------------
extern "C" void kernel_launch(void* const* d_in, const int* in_sizes, int n_in,
                              void* d_out, int out_size)
{
    const float* enc    = (const float*)d_in[0];
    const float* fhist  = (const float*)d_in[1];
    const float* ffut   = (const float*)d_in[3];
    const float* hidden = (const float*)d_in[4];
    const float* cell   = (const float*)d_in[5];
    const float* aW1    = (const float*)d_in[6];
    const float* ab1    = (const float*)d_in[7];
    const float* aW2    = (const float*)d_in[8];
    const float* ab2    = (const float*)d_in[9];
    const float* Wih    = (const float*)d_in[10];
    const float* Whh    = (const float*)d_in[11];
    const float* bih    = (const float*)d_in[12];
    const float* bhh    = (const float*)d_in[13];
    const float* fW1    = (const float*)d_in[14];
    const float* fb1    = (const float*)d_in[15];
    const float* fW2    = (const float*)d_in[16];
    const float* fb2    = (const float*)d_in[17];
    float* out = (float*)d_out;

    __half *pX1, *pTmp, *pX2, *pAW2, *pWcat, *pWcomb;
    unsigned char* pEnc8;
    float *pLog, *pAlpha, *pC, *pBias2, *pBcomb;
    cudaGetSymbolAddress((void**)&pX1, g_X1h);
    cudaGetSymbolAddress((void**)&pTmp, g_tmph);
    cudaGetSymbolAddress((void**)&pX2, g_X2h);
    cudaGetSymbolAddress((void**)&pAW2, g_aW2h);
    cudaGetSymbolAddress((void**)&pWcat, g_Wcath);
    cudaGetSymbolAddress((void**)&pWcomb, g_Wcombh);
    cudaGetSymbolAddress((void**)&pEnc8, g_enc8);
    cudaGetSymbolAddress((void**)&pLog, g_logits);
    cudaGetSymbolAddress((void**)&pAlpha, g_alpha);
    cudaGetSymbolAddress((void**)&pC, g_c);
    cudaGetSymbolAddress((void**)&pBias2, g_bias2);
    cudaGetSymbolAddress((void**)&pBcomb, g_bcomb);

    cudaFuncSetAttribute(hgemm2<32, 0, 1>, cudaFuncAttributeMaxDynamicSharedMemorySize, SMEM32_1);
    cudaFuncSetAttribute(hgemm2<32, 4, 2>, cudaFuncAttributeMaxDynamicSharedMemorySize, SMEM32_2);
    cudaFuncSetAttribute(hgemm2<64, 2, 2>, cudaFuncAttributeMaxDynamicSharedMemorySize, SMEM64_2);

    setup_kernel<<<512, 256>>>(hidden, cell, ffut, fb2, out, pC, pX1, pX2);
    alpha_kernel<<<NB, 576>>>(ffut, fhist, pAlpha);
    wcat_kernel<<<4096, 256>>>(Wih, Whh, bih, bhh, pWcat, pBias2);
    wcomb_kernel<<<1024, 256>>>(aW1, ab1, fW1, fb1, pWcomb, pBcomb);
    conv_half<<<1024, 256>>>(aW2, pAW2, NT * NT);
    conv_fp8<<<4096, 256>>>((const float4*)enc, (unsigned*)pEnc8, (int)((long)NB * NT * NE / 4));

    for (int t = 0; t < NFT; t++) {
        __half* X2cur = pX2 + (t & 1) * sX2B;
        __half* X2nxt = pX2 + ((t + 1) & 1) * sX2B;

        // combined: tmp = tanh(X1 @ aW1^T + ab1); fc for step t-1 (skipped at t=0)
        launch_pdl(hgemm2<32, 4, 2>, dim3(NB / BM, NC / 32, 1), dim3(128), (size_t)SMEM32_2,
            pX1, (const __half*)pWcomb, (const __half*)(pWcomb + oWcomb), (const float*)pBcomb,
            KX1, NT, 0L, 0L, 0L,
            (float*)nullptr, 0L, pTmp,
            (float*)nullptr, (__half*)nullptr, (__half*)nullptr, fW2, out, t - 1, 0);
        // attn2: logits = tmp @ aW2^T + ab2 (fp32, plain fp16 weights)
        launch_pdl(hgemm2<32, 0, 1>, dim3(NB / BM, NT / 32, 1), dim3(128), (size_t)SMEM32_1,
            (const __half*)pTmp, (const __half*)pAW2, (const __half*)pAW2, ab2,
            NT, NT, 0L, 0L, 0L,
            pLog, 0L, (__half*)nullptr,
            (float*)nullptr, (__half*)nullptr, (__half*)nullptr, (const float*)nullptr,
            (float*)nullptr, 0, 0);
        // ctx -> X2cur; scatters ff[t] into X2cur, ff[t+1] into X1
        const float* ffN = (t + 1 < NFT) ? (ffut + (t + 1) * NM) : nullptr;
        launch_pdl(ctx_kernel, dim3(NB), dim3(128), (size_t)0,
            (const float*)pLog, (const float*)pAlpha, (const unsigned char*)pEnc8,
            X2cur, pX1, (const float*)(ffut + t * NM), ffN);
        // gates GEMM + fused LSTM cell; h -> X1 / X2nxt, c updated
        launch_pdl(hgemm2<64, 2, 2>, dim3(NB / BM, G4 / 64, 2), dim3(128), (size_t)SMEM64_2,
            (const __half*)X2cur, (const __half*)pWcat, (const __half*)(pWcat + oWcat),
            (const float*)pBias2,
            KX2, G4, (long)NB * KX2, (long)G4 * KX2, (long)G4,
            (float*)nullptr, 0L, (__half*)nullptr,
            pC, pX1, X2nxt, (const float*)nullptr, (float*)nullptr, 0, 0);
    }
    // tail: fc for the last step (t = 23), fc columns only
    launch_pdl(hgemm2<32, 4, 2>, dim3(NB / BM, NH / 32, 1), dim3(128), (size_t)SMEM32_2,
        pX1, (const __half*)pWcomb, (const __half*)(pWcomb + oWcomb), (const float*)pBcomb,
        KX1, NT, 0L, 0L, 0L,
        (float*)nullptr, 0L, pTmp,
        (float*)nullptr, (__half*)nullptr, (__half*)nullptr, fW2, out, NFT - 1, NT / 32);
    (void)in_sizes; (void)n_in; (void)out_size;
}

// round 16
// speedup vs baseline: 1.1930x; 1.1930x over previous
#include <cuda_runtime.h>
#include <cuda_fp16.h>
#include <mma.h>
using namespace nvcuda;

// ---------------- problem constants ----------------
constexpr int NB   = 256;
constexpr int NT   = 576;
constexpr int NFT  = 24;
constexpr int NM   = 32;
constexpr int NH   = 256;
constexpr int NE   = 512;
constexpr int KX1  = 544;
constexpr int KX2  = 800;
constexpr int G4   = 1024;
constexpr int NC   = NT + NH;   // 832 combined attn1+fc columns
constexpr float EPSC = 1e-6f;

constexpr int BM = 32;
constexpr int KT = 32;
constexpr int SK = KT + 8;   // smem half row stride
constexpr int ST = 4;        // pipeline stages

// offsets
constexpr int sX2B = 2 * NB * KX2;       // stride between X2 ping-pong buffers
constexpr int oWcat = 2 * G4 * KX2;      // lo offset (split weights)
constexpr int oWcomb = NC * KX1;

// ---------------- scratch (device globals) ----------------
__device__ __align__(16) __half g_X1h[NB * KX1];          // plain fp16 activations
__device__ __align__(16) __half g_tmph[NB * NT];
__device__ __align__(16) __half g_X2h[2 * sX2B];          // ping-pong
__device__ __align__(16) __half g_aW2h[NT * NT];          // attn2 weights plain fp16
__device__ __align__(16) __half g_Wcath[2 * 2 * G4 * KX2];
__device__ __align__(16) __half g_Wcombh[2 * NC * KX1];
__device__ __align__(16) unsigned char g_enc8[(long)NB * NT * NE];  // enc fp8 e4m3
__device__ __align__(16) float g_logits[NB * NT];
__device__ __align__(16) float g_alpha[NB * NFT];
__device__ __align__(16) float g_c[2 * NB * NH];
__device__ __align__(16) float g_bias2[2 * G4];
__device__ __align__(16) float g_bcomb[NC];

__device__ __forceinline__ float sigm(float x) { return 1.0f / (1.0f + expf(-x)); }
__device__ __forceinline__ void fsplit(float v, __half& hi, __half& lo) {
    hi = __float2half(v);
    lo = __float2half(v - __half2float(hi));
}
__device__ __forceinline__ void cpa16(void* d, const void* s) {
    unsigned sd = (unsigned)__cvta_generic_to_shared(d);
    asm volatile("cp.async.cg.shared.global [%0], [%1], 16;" :: "r"(sd), "l"(s));
}
__device__ __forceinline__ void cp_commit() { asm volatile("cp.async.commit_group;"); }
template<int N_> __device__ __forceinline__ void cp_wait() {
    asm volatile("cp.async.wait_group %0;" :: "n"(N_));
}
__device__ __forceinline__ unsigned short f2_to_fp8x2(float hi, float lo) {
    unsigned short r;
    asm("cvt.rn.satfinite.e4m3x2.f32 %0, %1, %2;" : "=h"(r) : "f"(hi), "f"(lo));
    return r;
}
__device__ __forceinline__ __half2 fp8x2_to_half2(unsigned short v) {
    unsigned r;
    asm("cvt.rn.f16x2.e4m3x2 %0, %1;" : "=r"(r) : "h"(v));
    return *reinterpret_cast<__half2*>(&r);
}

// ---------------- one-time setup ----------------
__global__ void setup_kernel(const float* __restrict__ hidden, const float* __restrict__ cell,
                             const float* __restrict__ ff, const float* __restrict__ fb2,
                             float* __restrict__ out, float* __restrict__ c,
                             __half* __restrict__ X1, __half* __restrict__ X2)
{
    const int N0 = NB * NFT;
    const int N1 = 2 * NB * NH;
    const int N2 = NB * KX1;
    const int N3 = 2 * NB * 288;
    const int total = N0 + N1 + N2 + N3;
    for (int i = blockIdx.x * blockDim.x + threadIdx.x; i < total; i += gridDim.x * blockDim.x) {
        int r = i;
        if (r < N0) { out[r] = fb2[0]; continue; }
        r -= N0;
        if (r < N1) { c[r] = cell[r]; continue; }
        r -= N1;
        if (r < N2) {
            int b = r / KX1, k = r % KX1;
            float v;
            if (k < 512) v = hidden[(k < 256 ? 0 : 1) * NB * NH + b * NH + (k & 255)];
            else         v = ff[b * NFT * NM + (k - 512)];
            X1[r] = __float2half(v); continue;
        }
        r -= N2;
        int d = r / (NB * 288); int r2 = r % (NB * 288);
        int b = r2 / 288, k = r2 % 288;
        float v = (k < NM) ? ff[b * NFT * NM + k]
                           : hidden[d * NB * NH + b * NH + (k - NM)];
        X2[(d * NB + b) * KX2 + 512 + k] = __float2half(v);
    }
}

// ---------------- alpha (once) ----------------
__global__ void alpha_kernel(const float* __restrict__ ff, const float* __restrict__ fh,
                             float* __restrict__ alpha)
{
    int b = blockIdx.x, tid = threadIdx.x;
    int f = tid / 24, p = tid % 24;
    __shared__ float dist[24][24];
    __shared__ float dp[24];
    const float* x = ff + (b * NFT + f) * NM;
    const float* y = fh + ((long)b * NT + p * 24 + f) * NM;
    float s = 0.0f;
#pragma unroll
    for (int m = 0; m < NM; m++) { float d = x[m] - y[m] + EPSC; s += d * d; }
    dist[f][p] = sqrtf(s);
    __syncthreads();
    if (p == 0) { float t = 0.0f; for (int q = 0; q < 24; q++) t += dist[f][q]; dp[f] = 1.0f / t; }
    __syncthreads();
    if (tid == 0) {
        float mx = -1e30f;
        for (int q = 0; q < 24; q++) mx = fmaxf(mx, dp[q]);
        float e[24]; float ss = 0.0f;
        for (int q = 0; q < 24; q++) { e[q] = expf(dp[q] - mx); ss += e[q]; }
        float inv = 1.0f / ss;
        for (int q = 0; q < 24; q++) alpha[b * 24 + q] = e[q] * inv;
    }
}

// ---------------- pack gate-interleaved [W_ih | W_hh] split + combined bias ----------------
__global__ void wcat_kernel(const float* __restrict__ Wih, const float* __restrict__ Whh,
                            const float* __restrict__ bih, const float* __restrict__ bhh,
                            __half* __restrict__ Wcat, float* __restrict__ bias2)
{
    const int total = 2 * G4 * KX2;
    for (int i = blockIdx.x * blockDim.x + threadIdx.x; i < total; i += gridDim.x * blockDim.x) {
        int d = i / (G4 * KX2); int r = i % (G4 * KX2);
        int np = r / KX2, k = r % KX2;
        int n = (np & 3) * 256 + (np >> 2);
        float v = (k < KX1) ? Wih[(long)(d * G4 + n) * KX1 + k]
                            : Whh[(long)(d * G4 + n) * NH + (k - KX1)];
        __half h, l; fsplit(v, h, l);
        Wcat[i] = h; Wcat[total + i] = l;
    }
    int tid = blockIdx.x * blockDim.x + threadIdx.x;
    if (tid < 2 * G4) {
        int d = tid / G4, np = tid % G4;
        int n = (np & 3) * 256 + (np >> 2);
        bias2[tid] = bih[d * G4 + n] + bhh[d * G4 + n];
    }
}

// ---------------- pack combined [aW1 ; fW1 zero-padded] + bias (once) ----------------
__global__ void wcomb_kernel(const float* __restrict__ aW1, const float* __restrict__ ab1,
                             const float* __restrict__ fW1, const float* __restrict__ fb1,
                             __half* __restrict__ Wc, float* __restrict__ bc)
{
    const int total = NC * KX1;
    for (int i = blockIdx.x * blockDim.x + threadIdx.x; i < total; i += gridDim.x * blockDim.x) {
        int n = i / KX1, k = i % KX1;
        float v;
        if (n < NT) v = aW1[n * KX1 + k];
        else        v = (k < NE) ? fW1[(n - NT) * NE + k] : 0.0f;
        __half h, l; fsplit(v, h, l);
        Wc[i] = h; Wc[total + i] = l;
    }
    int tid = blockIdx.x * blockDim.x + threadIdx.x;
    if (tid < NC) bc[tid] = (tid < NT) ? ab1[tid] : fb1[tid - NT];
}

// ---------------- converters ----------------
__global__ void conv_half(const float* __restrict__ src, __half* __restrict__ dst, int n)
{
    for (int i = blockIdx.x * blockDim.x + threadIdx.x; i < n; i += gridDim.x * blockDim.x)
        dst[i] = __float2half(src[i]);
}

__global__ void conv_fp8(const float4* __restrict__ src, unsigned* __restrict__ dst, int n4)
{
    for (int i = blockIdx.x * blockDim.x + threadIdx.x; i < n4; i += gridDim.x * blockDim.x) {
        float4 v = src[i];
        unsigned short s01 = f2_to_fp8x2(v.y, v.x);
        unsigned short s23 = f2_to_fp8x2(v.w, v.z);
        dst[i] = (unsigned)s01 | ((unsigned)s23 << 16);
    }
}

// ---------------- 4-stage fp16-A x fp16/split-W tensor-core GEMM ----------------
// NW = 1 (plain W) or 2 (split W hi+lo, independent accumulators).
// Fused per-stage commits (A+W in one group) — R13 pipeline structure.
// EPI: 0 fp32 out (attn2), 2 LSTM cell (BN=64, gate-interleaved),
//      4 combined attn1+fc: cols<NT -> tanh to tmp; cols>=NT -> relu.w2 -> out
template<int BN, int EPI, int NW>
__global__ __launch_bounds__(128) void hgemm2(
    const __half* __restrict__ Ah, const __half* __restrict__ Whi, const __half* __restrict__ Wlo,
    const float* __restrict__ bias, int K, int N,
    long sA, long sW, long sB,
    float* __restrict__ Cf, long sC, __half* __restrict__ Ch,
    float* __restrict__ cst, __half* __restrict__ X1, __half* __restrict__ X2out,
    const float* __restrict__ w2, float* __restrict__ out, int tstep, int yoff)
{
    const long z = blockIdx.z;
    Ah += z * sA; Whi += z * sW; Wlo += z * sW; bias += z * sB;
    extern __shared__ char dsm[];
    __half* As = (__half*)dsm;                         // [ST][BM][SK]
    __half* Ws = As + ST * BM * SK;                    // [ST][NW][BN][SK]
    float*  Cs = (float*)(Ws + ST * NW * BN * SK);     // [BM][BN+4]
    float*  red = Cs + BM * (BN + 4);                  // [128]
    auto ap = [&](int st, int r) { return As + (st * BM + r) * SK; };
    auto wp = [&](int st, int hf, int r) { return Ws + ((st * NW + hf) * BN + r) * SK; };

    const int tid = threadIdx.x;
    const int m0 = blockIdx.x * BM, n0 = (blockIdx.y + yoff) * BN;
    const int warp = tid >> 5, wm = warp >> 1, wn = warp & 1;
    const int ar = tid >> 2, ac = (tid & 3) * 8;
    const int nk = K / KT;

    wmma::fragment<wmma::accumulator, 16, 16, 16, float> acc0[NW], acc1[NW];
#pragma unroll
    for (int q = 0; q < NW; q++) {
        wmma::fill_fragment(acc0[q], 0.0f);
        if (BN == 64) wmma::fill_fragment(acc1[q], 0.0f);
    }

    auto stage_load = [&](int st, int kt) {
        const int k0 = kt * KT;
        cpa16(ap(st, ar) + ac, Ah + (long)(m0 + ar) * K + k0 + ac);
        cpa16(wp(st, 0, ar) + ac, Whi + (long)(n0 + ar) * K + k0 + ac);
        if (NW == 2) cpa16(wp(st, 1, ar) + ac, Wlo + (long)(n0 + ar) * K + k0 + ac);
        if (BM < BN) {  // BN=64: extra W rows
            cpa16(wp(st, 0, ar + BM) + ac, Whi + (long)(n0 + ar + BM) * K + k0 + ac);
            if (NW == 2) cpa16(wp(st, 1, ar + BM) + ac, Wlo + (long)(n0 + ar + BM) * K + k0 + ac);
        }
        cp_commit();
    };

    stage_load(0, 0);
    stage_load(1, 1);
    stage_load(2, 2);

    for (int kt = 0; kt < nk; kt++) {
        const int cur = kt % ST;
        if (kt + 3 < nk) {
            stage_load((kt + 3) % ST, kt + 3);
            cp_wait<3>();
        } else if (kt + 2 < nk) {
            cp_wait<2>();
        } else if (kt + 1 < nk) {
            cp_wait<1>();
        } else {
            cp_wait<0>();
        }
        __syncthreads();
#pragma unroll
        for (int sub = 0; sub < KT; sub += 16) {
            wmma::fragment<wmma::matrix_a, 16, 16, 16, __half, wmma::row_major> ah;
            wmma::load_matrix_sync(ah, ap(cur, wm * 16) + sub, SK);
            wmma::fragment<wmma::matrix_b, 16, 16, 16, __half, wmma::col_major> bh, bl;
            if (BN == 64) {
                wmma::load_matrix_sync(bh, wp(cur, 0, wn * 32) + sub, SK);
                wmma::mma_sync(acc0[0], ah, bh, acc0[0]);
                if (NW == 2) {
                    wmma::load_matrix_sync(bl, wp(cur, 1, wn * 32) + sub, SK);
                    wmma::mma_sync(acc0[1], ah, bl, acc0[1]);
                }
                wmma::load_matrix_sync(bh, wp(cur, 0, wn * 32 + 16) + sub, SK);
                wmma::mma_sync(acc1[0], ah, bh, acc1[0]);
                if (NW == 2) {
                    wmma::load_matrix_sync(bl, wp(cur, 1, wn * 32 + 16) + sub, SK);
                    wmma::mma_sync(acc1[1], ah, bl, acc1[1]);
                }
            } else {
                wmma::load_matrix_sync(bh, wp(cur, 0, wn * 16) + sub, SK);
                wmma::mma_sync(acc0[0], ah, bh, acc0[0]);
                if (NW == 2) {
                    wmma::load_matrix_sync(bl, wp(cur, 1, wn * 16) + sub, SK);
                    wmma::mma_sync(acc0[1], ah, bl, acc0[1]);
                }
            }
        }
        __syncthreads();
    }

    if (NW == 2) {
#pragma unroll
        for (int e = 0; e < acc0[0].num_elements; e++) {
            acc0[0].x[e] += acc0[1].x[e];
            if (BN == 64) acc1[0].x[e] += acc1[1].x[e];
        }
    }
    if (BN == 64) {
        wmma::store_matrix_sync(Cs + (wm * 16) * (BN + 4) + wn * 32, acc0[0], BN + 4, wmma::mem_row_major);
        wmma::store_matrix_sync(Cs + (wm * 16) * (BN + 4) + wn * 32 + 16, acc1[0], BN + 4, wmma::mem_row_major);
    } else {
        wmma::store_matrix_sync(Cs + (wm * 16) * (BN + 4) + wn * 16, acc0[0], BN + 4, wmma::mem_row_major);
    }
    __syncthreads();

    if (EPI == 0) {
        for (int idx = tid; idx < BM * BN; idx += 128) {
            int m = idx / BN, n = idx % BN;
            Cf[(long)(m0 + m) * N + n0 + n + z * sC] = Cs[m * (BN + 4) + n] + bias[n0 + n];
        }
    } else if (EPI == 2) {
        const int d = (int)z;
        for (int idx = tid; idx < BM * 16; idx += 128) {
            int m = idx >> 4, jj = idx & 15;
            int b = m0 + m, j = (n0 >> 2) + jj;
            float ig = sigm(Cs[m * (BN + 4) + jj * 4 + 0] + bias[n0 + jj * 4 + 0]);
            float fg = sigm(Cs[m * (BN + 4) + jj * 4 + 1] + bias[n0 + jj * 4 + 1]);
            float gg = tanhf(Cs[m * (BN + 4) + jj * 4 + 2] + bias[n0 + jj * 4 + 2]);
            float og = sigm(Cs[m * (BN + 4) + jj * 4 + 3] + bias[n0 + jj * 4 + 3]);
            int ci = (d * NB + b) * NH + j;
            float cn = fg * cst[ci] + ig * gg;
            float hn = og * tanhf(cn);
            cst[ci] = cn;
            __half h = __float2half(hn);
            X2out[(d * NB + b) * KX2 + 544 + j] = h;   // into NEXT X2 buffer
            X1[b * KX1 + d * NH + j] = h;              // into X1 (hh slice)
        }
    } else {  // EPI == 4, BN == 32: combined attn1 + fc
        if (n0 < NT) {
            for (int idx = tid; idx < BM * BN; idx += 128) {
                int m = idx / BN, n = idx % BN;
                float v = tanhf(Cs[m * (BN + 4) + n] + bias[n0 + n]);
                Ch[(long)(m0 + m) * NT + n0 + n] = __float2half(v);
            }
        } else if (tstep >= 0) {
            int r = tid >> 2, g = tid & 3;
            float s = 0.0f;
#pragma unroll
            for (int jj = 0; jj < 8; jj++) {
                int n = g * 8 + jj;
                float v = fmaxf(Cs[r * (BN + 4) + n] + bias[n0 + n], 0.0f);
                s += v * w2[n0 - NT + n];
            }
            red[tid] = s;
            __syncthreads();
            if (tid < 32) {
                float t = red[tid * 4] + red[tid * 4 + 1] + red[tid * 4 + 2] + red[tid * 4 + 3];
                atomicAdd(&out[(m0 + tid) * NFT + tstep], t);
            }
        }
    }
}

constexpr int smem_sz(int bn, int nw) {
    return (ST * BM * SK + ST * nw * bn * SK) * 2 + BM * (bn + 4) * 4 + 128 * 4 + 256;
}
constexpr int SMEM32_2 = smem_sz(32, 2);
constexpr int SMEM32_1 = smem_sz(32, 1);
constexpr int SMEM64_2 = smem_sz(64, 2);

// ---------------- ctx: one block per batch row; softmax once; fp8 enc stream ----------------
__global__ __launch_bounds__(128) void ctx_kernel(
    const float* __restrict__ logits, const float* __restrict__ alpha,
    const unsigned char* __restrict__ enc8, __half* __restrict__ X2h, __half* __restrict__ X1h,
    const float* __restrict__ ffC, const float* __restrict__ ffN)
{
    const int b = blockIdx.x;
    const int tid = threadIdx.x;
    __shared__ float wt[NT];
    __shared__ float sred[4];
    const float* lrow = logits + b * NT;

    float mx = -1e30f;
    for (int t = tid; t < NT; t += 128) mx = fmaxf(mx, lrow[t]);
#pragma unroll
    for (int o = 16; o > 0; o >>= 1) mx = fmaxf(mx, __shfl_xor_sync(0xffffffffu, mx, o));
    if ((tid & 31) == 0) sred[tid >> 5] = mx;
    __syncthreads();
    mx = fmaxf(fmaxf(sred[0], sred[1]), fmaxf(sred[2], sred[3]));
    __syncthreads();

    float s = 0.0f;
    for (int t = tid; t < NT; t += 128) { float e = expf(lrow[t] - mx); wt[t] = e; s += e; }
#pragma unroll
    for (int o = 16; o > 0; o >>= 1) s += __shfl_xor_sync(0xffffffffu, s, o);
    if ((tid & 31) == 0) sred[tid >> 5] = s;
    __syncthreads();
    s = sred[0] + sred[1] + sred[2] + sred[3];
    float inv = 1.0f / s;
    for (int t = tid; t < NT; t += 128) wt[t] *= inv * alpha[b * 24 + t / 24];
    __syncthreads();

    // 4 columns per thread (128 thr x 4 = 512 cols), fp8 packed as uint
    const unsigned* eb = (const unsigned*)(enc8 + (long)b * NT * NE) + tid;
    float a0 = 0, a1 = 0, a2 = 0, a3 = 0;
#pragma unroll 1
    for (int t = 0; t < NT; t += 8) {
        unsigned q0 = eb[(t + 0) * 128];
        unsigned q1 = eb[(t + 1) * 128];
        unsigned q2 = eb[(t + 2) * 128];
        unsigned q3 = eb[(t + 3) * 128];
        unsigned q4 = eb[(t + 4) * 128];
        unsigned q5 = eb[(t + 5) * 128];
        unsigned q6 = eb[(t + 6) * 128];
        unsigned q7 = eb[(t + 7) * 128];
#pragma unroll
        for (int i = 0; i < 8; i++) {
            unsigned q = (i == 0) ? q0 : (i == 1) ? q1 : (i == 2) ? q2 : (i == 3) ? q3
                       : (i == 4) ? q4 : (i == 5) ? q5 : (i == 6) ? q6 : q7;
            float w = wt[t + i];
            float2 f01 = __half22float2(fp8x2_to_half2((unsigned short)(q & 0xffff)));
            float2 f23 = __half22float2(fp8x2_to_half2((unsigned short)(q >> 16)));
            a0 += w * f01.x; a1 += w * f01.y; a2 += w * f23.x; a3 += w * f23.y;
        }
    }
    __half2 p01 = __floats2half2_rn(a0, a1);
    __half2 p23 = __floats2half2_rn(a2, a3);
    long o0 = (long)b * KX2 + 4 * tid;
    long o1 = (long)(NB + b) * KX2 + 4 * tid;
    *(__half2*)(X2h + o0) = p01; *(__half2*)(X2h + o0 + 2) = p23;
    *(__half2*)(X2h + o1) = p01; *(__half2*)(X2h + o1 + 2) = p23;

    if (tid < NM) {
        __half h = __float2half(ffC[b * NFT * NM + tid]);
        X2h[(long)b * KX2 + 512 + tid] = h;
        X2h[(long)(NB + b) * KX2 + 512 + tid] = h;
        if (ffN != nullptr)
            X1h[b * KX1 + 512 + tid] = __float2half(ffN[b * NFT * NM + tid]);
    }
}

// ---------------- launch ----------------
extern "C" void kernel_launch(void* const* d_in, const int* in_sizes, int n_in,
                              void* d_out, int out_size)
{
    const float* enc    = (const float*)d_in[0];
    const float* fhist  = (const float*)d_in[1];
    const float* ffut   = (const float*)d_in[3];
    const float* hidden = (const float*)d_in[4];
    const float* cell   = (const float*)d_in[5];
    const float* aW1    = (const float*)d_in[6];
    const float* ab1    = (const float*)d_in[7];
    const float* aW2    = (const float*)d_in[8];
    const float* ab2    = (const float*)d_in[9];
    const float* Wih    = (const float*)d_in[10];
    const float* Whh    = (const float*)d_in[11];
    const float* bih    = (const float*)d_in[12];
    const float* bhh    = (const float*)d_in[13];
    const float* fW1    = (const float*)d_in[14];
    const float* fb1    = (const float*)d_in[15];
    const float* fW2    = (const float*)d_in[16];
    const float* fb2    = (const float*)d_in[17];
    float* out = (float*)d_out;

    __half *pX1, *pTmp, *pX2, *pAW2, *pWcat, *pWcomb;
    unsigned char* pEnc8;
    float *pLog, *pAlpha, *pC, *pBias2, *pBcomb;
    cudaGetSymbolAddress((void**)&pX1, g_X1h);
    cudaGetSymbolAddress((void**)&pTmp, g_tmph);
    cudaGetSymbolAddress((void**)&pX2, g_X2h);
    cudaGetSymbolAddress((void**)&pAW2, g_aW2h);
    cudaGetSymbolAddress((void**)&pWcat, g_Wcath);
    cudaGetSymbolAddress((void**)&pWcomb, g_Wcombh);
    cudaGetSymbolAddress((void**)&pEnc8, g_enc8);
    cudaGetSymbolAddress((void**)&pLog, g_logits);
    cudaGetSymbolAddress((void**)&pAlpha, g_alpha);
    cudaGetSymbolAddress((void**)&pC, g_c);
    cudaGetSymbolAddress((void**)&pBias2, g_bias2);
    cudaGetSymbolAddress((void**)&pBcomb, g_bcomb);

    cudaFuncSetAttribute(hgemm2<32, 0, 1>, cudaFuncAttributeMaxDynamicSharedMemorySize, SMEM32_1);
    cudaFuncSetAttribute(hgemm2<32, 4, 2>, cudaFuncAttributeMaxDynamicSharedMemorySize, SMEM32_2);
    cudaFuncSetAttribute(hgemm2<64, 2, 2>, cudaFuncAttributeMaxDynamicSharedMemorySize, SMEM64_2);

    setup_kernel<<<512, 256>>>(hidden, cell, ffut, fb2, out, pC, pX1, pX2);
    alpha_kernel<<<NB, 576>>>(ffut, fhist, pAlpha);
    wcat_kernel<<<4096, 256>>>(Wih, Whh, bih, bhh, pWcat, pBias2);
    wcomb_kernel<<<1024, 256>>>(aW1, ab1, fW1, fb1, pWcomb, pBcomb);
    conv_half<<<1024, 256>>>(aW2, pAW2, NT * NT);
    conv_fp8<<<4096, 256>>>((const float4*)enc, (unsigned*)pEnc8, (int)((long)NB * NT * NE / 4));

    for (int t = 0; t < NFT; t++) {
        __half* X2cur = pX2 + (t & 1) * sX2B;
        __half* X2nxt = pX2 + ((t + 1) & 1) * sX2B;

        // combined: tmp = tanh(X1 @ aW1^T + ab1); fc for step t-1 (skipped at t=0)
        hgemm2<32, 4, 2><<<dim3(NB / BM, NC / 32, 1), 128, SMEM32_2>>>(
            pX1, pWcomb, pWcomb + oWcomb, pBcomb, KX1, NT, 0, 0, 0,
            nullptr, 0, pTmp,
            nullptr, nullptr, nullptr, fW2, out, t - 1, 0);
        // attn2: logits = tmp @ aW2^T + ab2 (fp32, plain fp16 weights, 1 mma term)
        hgemm2<32, 0, 1><<<dim3(NB / BM, NT / 32, 1), 128, SMEM32_1>>>(
            pTmp, pAW2, pAW2, ab2, NT, NT, 0, 0, 0,
            pLog, 0, nullptr,
            nullptr, nullptr, nullptr, nullptr, nullptr, 0, 0);
        // ctx -> X2cur; scatters ff[t] into X2cur, ff[t+1] into X1
        const float* ffN = (t + 1 < NFT) ? (ffut + (t + 1) * NM) : nullptr;
        ctx_kernel<<<NB, 128>>>(pLog, pAlpha, pEnc8, X2cur, pX1,
                                ffut + t * NM, ffN);
        // gates GEMM + fused LSTM cell; h -> X1 / X2nxt, c updated
        hgemm2<64, 2, 2><<<dim3(NB / BM, G4 / 64, 2), 128, SMEM64_2>>>(
            X2cur, pWcat, pWcat + oWcat, pBias2, KX2, G4,
            (long)NB * KX2, (long)G4 * KX2, (long)G4,
            nullptr, 0, nullptr,
            pC, pX1, X2nxt, nullptr, nullptr, 0, 0);
    }
    // tail: fc for the last step (t = 23), fc columns only
    hgemm2<32, 4, 2><<<dim3(NB / BM, NH / 32, 1), 128, SMEM32_2>>>(
        pX1, pWcomb, pWcomb + oWcomb, pBcomb, KX1, NT, 0, 0, 0,
        nullptr, 0, pTmp,
        nullptr, nullptr, nullptr, fW2, out, NFT - 1, NT / 32);
    (void)in_sizes; (void)n_in; (void)out_size;
}

// round 17
// speedup vs baseline: 1.2049x; 1.0100x over previous
#include <cuda_runtime.h>
#include <cuda_fp16.h>
#include <mma.h>
using namespace nvcuda;

// ---------------- problem constants ----------------
constexpr int NB   = 256;
constexpr int NT   = 576;
constexpr int NFT  = 24;
constexpr int NM   = 32;
constexpr int NH   = 256;
constexpr int NE   = 512;
constexpr int KX1  = 544;
constexpr int KX2  = 800;
constexpr int G4   = 1024;
constexpr int NC   = NT + NH;   // 832 combined attn1+fc columns
constexpr float EPSC = 1e-6f;

constexpr int BM = 32;
constexpr int KT = 32;
constexpr int SK = KT + 8;   // smem half row stride
constexpr int ST = 4;        // pipeline stages

// offsets
constexpr int sX2B = 2 * NB * KX2;       // stride between X2 ping-pong buffers
constexpr int oWcat = 2 * G4 * KX2;      // lo offset (split weights)
constexpr int oWcomb = NC * KX1;

// ---------------- scratch (device globals) ----------------
__device__ __align__(16) __half g_X1h[NB * KX1];          // plain fp16 activations
__device__ __align__(16) __half g_tmph[NB * NT];
__device__ __align__(16) __half g_X2h[2 * sX2B];          // ping-pong
__device__ __align__(16) __half g_aW2h[NT * NT];          // attn2 weights plain fp16
__device__ __align__(16) __half g_Wcath[2 * 2 * G4 * KX2];
__device__ __align__(16) __half g_Wcombh[2 * NC * KX1];
__device__ __align__(16) unsigned char g_enc8[(long)NB * NT * NE];  // enc fp8 e4m3
__device__ __align__(16) float g_logits[NB * NT];
__device__ __align__(16) float g_alpha[NB * NFT];
__device__ __align__(16) float g_c[2 * NB * NH];
__device__ __align__(16) float g_bias2[2 * G4];
__device__ __align__(16) float g_bcomb[NC];

__device__ __forceinline__ float sigm(float x) { return 1.0f / (1.0f + expf(-x)); }
__device__ __forceinline__ void fsplit(float v, __half& hi, __half& lo) {
    hi = __float2half(v);
    lo = __float2half(v - __half2float(hi));
}
__device__ __forceinline__ void cpa16(void* d, const void* s) {
    unsigned sd = (unsigned)__cvta_generic_to_shared(d);
    asm volatile("cp.async.cg.shared.global [%0], [%1], 16;" :: "r"(sd), "l"(s));
}
__device__ __forceinline__ void cp_commit() { asm volatile("cp.async.commit_group;"); }
template<int N_> __device__ __forceinline__ void cp_wait() {
    asm volatile("cp.async.wait_group %0;" :: "n"(N_));
}
__device__ __forceinline__ unsigned short f2_to_fp8x2(float hi, float lo) {
    unsigned short r;
    asm("cvt.rn.satfinite.e4m3x2.f32 %0, %1, %2;" : "=h"(r) : "f"(hi), "f"(lo));
    return r;
}
__device__ __forceinline__ __half2 fp8x2_to_half2(unsigned short v) {
    unsigned r;
    asm("cvt.rn.f16x2.e4m3x2 %0, %1;" : "=r"(r) : "h"(v));
    return *reinterpret_cast<__half2*>(&r);
}

// ---------------- one-time setup ----------------
__global__ void setup_kernel(const float* __restrict__ hidden, const float* __restrict__ cell,
                             const float* __restrict__ ff, const float* __restrict__ fb2,
                             float* __restrict__ out, float* __restrict__ c,
                             __half* __restrict__ X1, __half* __restrict__ X2)
{
    const int N0 = NB * NFT;
    const int N1 = 2 * NB * NH;
    const int N2 = NB * KX1;
    const int N3 = 2 * NB * 288;
    const int total = N0 + N1 + N2 + N3;
    for (int i = blockIdx.x * blockDim.x + threadIdx.x; i < total; i += gridDim.x * blockDim.x) {
        int r = i;
        if (r < N0) { out[r] = fb2[0]; continue; }
        r -= N0;
        if (r < N1) { c[r] = cell[r]; continue; }
        r -= N1;
        if (r < N2) {
            int b = r / KX1, k = r % KX1;
            float v;
            if (k < 512) v = hidden[(k < 256 ? 0 : 1) * NB * NH + b * NH + (k & 255)];
            else         v = ff[b * NFT * NM + (k - 512)];
            X1[r] = __float2half(v); continue;
        }
        r -= N2;
        int d = r / (NB * 288); int r2 = r % (NB * 288);
        int b = r2 / 288, k = r2 % 288;
        float v = (k < NM) ? ff[b * NFT * NM + k]
                           : hidden[d * NB * NH + b * NH + (k - NM)];
        X2[(d * NB + b) * KX2 + 512 + k] = __float2half(v);
    }
}

// ---------------- alpha (once) ----------------
__global__ void alpha_kernel(const float* __restrict__ ff, const float* __restrict__ fh,
                             float* __restrict__ alpha)
{
    int b = blockIdx.x, tid = threadIdx.x;
    int f = tid / 24, p = tid % 24;
    __shared__ float dist[24][24];
    __shared__ float dp[24];
    const float* x = ff + (b * NFT + f) * NM;
    const float* y = fh + ((long)b * NT + p * 24 + f) * NM;
    float s = 0.0f;
#pragma unroll
    for (int m = 0; m < NM; m++) { float d = x[m] - y[m] + EPSC; s += d * d; }
    dist[f][p] = sqrtf(s);
    __syncthreads();
    if (p == 0) { float t = 0.0f; for (int q = 0; q < 24; q++) t += dist[f][q]; dp[f] = 1.0f / t; }
    __syncthreads();
    if (tid == 0) {
        float mx = -1e30f;
        for (int q = 0; q < 24; q++) mx = fmaxf(mx, dp[q]);
        float e[24]; float ss = 0.0f;
        for (int q = 0; q < 24; q++) { e[q] = expf(dp[q] - mx); ss += e[q]; }
        float inv = 1.0f / ss;
        for (int q = 0; q < 24; q++) alpha[b * 24 + q] = e[q] * inv;
    }
}

// ---------------- pack gate-interleaved [W_ih | W_hh] split + combined bias ----------------
__global__ void wcat_kernel(const float* __restrict__ Wih, const float* __restrict__ Whh,
                            const float* __restrict__ bih, const float* __restrict__ bhh,
                            __half* __restrict__ Wcat, float* __restrict__ bias2)
{
    const int total = 2 * G4 * KX2;
    for (int i = blockIdx.x * blockDim.x + threadIdx.x; i < total; i += gridDim.x * blockDim.x) {
        int d = i / (G4 * KX2); int r = i % (G4 * KX2);
        int np = r / KX2, k = r % KX2;
        int n = (np & 3) * 256 + (np >> 2);
        float v = (k < KX1) ? Wih[(long)(d * G4 + n) * KX1 + k]
                            : Whh[(long)(d * G4 + n) * NH + (k - KX1)];
        __half h, l; fsplit(v, h, l);
        Wcat[i] = h; Wcat[total + i] = l;
    }
    int tid = blockIdx.x * blockDim.x + threadIdx.x;
    if (tid < 2 * G4) {
        int d = tid / G4, np = tid % G4;
        int n = (np & 3) * 256 + (np >> 2);
        bias2[tid] = bih[d * G4 + n] + bhh[d * G4 + n];
    }
}

// ---------------- pack combined [aW1 ; fW1 zero-padded] + bias (once) ----------------
__global__ void wcomb_kernel(const float* __restrict__ aW1, const float* __restrict__ ab1,
                             const float* __restrict__ fW1, const float* __restrict__ fb1,
                             __half* __restrict__ Wc, float* __restrict__ bc)
{
    const int total = NC * KX1;
    for (int i = blockIdx.x * blockDim.x + threadIdx.x; i < total; i += gridDim.x * blockDim.x) {
        int n = i / KX1, k = i % KX1;
        float v;
        if (n < NT) v = aW1[n * KX1 + k];
        else        v = (k < NE) ? fW1[(n - NT) * NE + k] : 0.0f;
        __half h, l; fsplit(v, h, l);
        Wc[i] = h; Wc[total + i] = l;
    }
    int tid = blockIdx.x * blockDim.x + threadIdx.x;
    if (tid < NC) bc[tid] = (tid < NT) ? ab1[tid] : fb1[tid - NT];
}

// ---------------- converters ----------------
__global__ void conv_half(const float* __restrict__ src, __half* __restrict__ dst, int n)
{
    for (int i = blockIdx.x * blockDim.x + threadIdx.x; i < n; i += gridDim.x * blockDim.x)
        dst[i] = __float2half(src[i]);
}

__global__ void conv_fp8(const float4* __restrict__ src, unsigned* __restrict__ dst, int n4)
{
    for (int i = blockIdx.x * blockDim.x + threadIdx.x; i < n4; i += gridDim.x * blockDim.x) {
        float4 v = src[i];
        unsigned short s01 = f2_to_fp8x2(v.y, v.x);
        unsigned short s23 = f2_to_fp8x2(v.w, v.z);
        dst[i] = (unsigned)s01 | ((unsigned)s23 << 16);
    }
}

// ---------------- 4-stage fp16-A x fp16/split-W tensor-core GEMM ----------------
// NW = 1 (plain W) or 2 (split W hi+lo). For EPI==4, the lo term is skipped at
// runtime for attn1 tiles (n0 < NT): softmax path is error-attenuated (measured).
// EPI: 0 fp32 out (attn2), 2 LSTM cell (BN=64, gate-interleaved),
//      4 combined attn1+fc: cols<NT -> tanh to tmp; cols>=NT -> relu.w2 -> out
template<int BN, int EPI, int NW>
__global__ __launch_bounds__(128) void hgemm2(
    const __half* __restrict__ Ah, const __half* __restrict__ Whi, const __half* __restrict__ Wlo,
    const float* __restrict__ bias, int K, int N,
    long sA, long sW, long sB,
    float* __restrict__ Cf, long sC, __half* __restrict__ Ch,
    float* __restrict__ cst, __half* __restrict__ X1, __half* __restrict__ X2out,
    const float* __restrict__ w2, float* __restrict__ out, int tstep, int yoff)
{
    const long z = blockIdx.z;
    Ah += z * sA; Whi += z * sW; Wlo += z * sW; bias += z * sB;
    extern __shared__ char dsm[];
    __half* As = (__half*)dsm;                         // [ST][BM][SK]
    __half* Ws = As + ST * BM * SK;                    // [ST][NW][BN][SK]
    float*  Cs = (float*)(Ws + ST * NW * BN * SK);     // [BM][BN+4]
    float*  red = Cs + BM * (BN + 4);                  // [128]
    auto ap = [&](int st, int r) { return As + (st * BM + r) * SK; };
    auto wp = [&](int st, int hf, int r) { return Ws + ((st * NW + hf) * BN + r) * SK; };

    const int tid = threadIdx.x;
    const int m0 = blockIdx.x * BM, n0 = (blockIdx.y + yoff) * BN;
    const int warp = tid >> 5, wm = warp >> 1, wn = warp & 1;
    const int ar = tid >> 2, ac = (tid & 3) * 8;
    const int nk = K / KT;

    // lo term active? (EPI4 attn1 tiles skip it — softmax-attenuated path)
    const bool useLo = (NW == 2) && (EPI != 4 || n0 >= NT);

    wmma::fragment<wmma::accumulator, 16, 16, 16, float> acc0[NW], acc1[NW];
#pragma unroll
    for (int q = 0; q < NW; q++) {
        wmma::fill_fragment(acc0[q], 0.0f);
        if (BN == 64) wmma::fill_fragment(acc1[q], 0.0f);
    }

    auto stage_load = [&](int st, int kt) {
        const int k0 = kt * KT;
        cpa16(ap(st, ar) + ac, Ah + (long)(m0 + ar) * K + k0 + ac);
        cpa16(wp(st, 0, ar) + ac, Whi + (long)(n0 + ar) * K + k0 + ac);
        if (NW == 2 && useLo) cpa16(wp(st, 1, ar) + ac, Wlo + (long)(n0 + ar) * K + k0 + ac);
        if (BM < BN) {  // BN=64: extra W rows
            cpa16(wp(st, 0, ar + BM) + ac, Whi + (long)(n0 + ar + BM) * K + k0 + ac);
            if (NW == 2 && useLo) cpa16(wp(st, 1, ar + BM) + ac, Wlo + (long)(n0 + ar + BM) * K + k0 + ac);
        }
        cp_commit();
    };

    stage_load(0, 0);
    stage_load(1, 1);
    stage_load(2, 2);

    for (int kt = 0; kt < nk; kt++) {
        const int cur = kt % ST;
        if (kt + 3 < nk) {
            stage_load((kt + 3) % ST, kt + 3);
            cp_wait<3>();
        } else if (kt + 2 < nk) {
            cp_wait<2>();
        } else if (kt + 1 < nk) {
            cp_wait<1>();
        } else {
            cp_wait<0>();
        }
        __syncthreads();
#pragma unroll
        for (int sub = 0; sub < KT; sub += 16) {
            wmma::fragment<wmma::matrix_a, 16, 16, 16, __half, wmma::row_major> ah;
            wmma::load_matrix_sync(ah, ap(cur, wm * 16) + sub, SK);
            wmma::fragment<wmma::matrix_b, 16, 16, 16, __half, wmma::col_major> bh, bl;
            if (BN == 64) {
                wmma::load_matrix_sync(bh, wp(cur, 0, wn * 32) + sub, SK);
                wmma::mma_sync(acc0[0], ah, bh, acc0[0]);
                if (NW == 2 && useLo) {
                    wmma::load_matrix_sync(bl, wp(cur, 1, wn * 32) + sub, SK);
                    wmma::mma_sync(acc0[1], ah, bl, acc0[1]);
                }
                wmma::load_matrix_sync(bh, wp(cur, 0, wn * 32 + 16) + sub, SK);
                wmma::mma_sync(acc1[0], ah, bh, acc1[0]);
                if (NW == 2 && useLo) {
                    wmma::load_matrix_sync(bl, wp(cur, 1, wn * 32 + 16) + sub, SK);
                    wmma::mma_sync(acc1[1], ah, bl, acc1[1]);
                }
            } else {
                wmma::load_matrix_sync(bh, wp(cur, 0, wn * 16) + sub, SK);
                wmma::mma_sync(acc0[0], ah, bh, acc0[0]);
                if (NW == 2 && useLo) {
                    wmma::load_matrix_sync(bl, wp(cur, 1, wn * 16) + sub, SK);
                    wmma::mma_sync(acc0[1], ah, bl, acc0[1]);
                }
            }
        }
        __syncthreads();
    }

    if (NW == 2 && useLo) {
#pragma unroll
        for (int e = 0; e < acc0[0].num_elements; e++) {
            acc0[0].x[e] += acc0[1].x[e];
            if (BN == 64) acc1[0].x[e] += acc1[1].x[e];
        }
    }
    if (BN == 64) {
        wmma::store_matrix_sync(Cs + (wm * 16) * (BN + 4) + wn * 32, acc0[0], BN + 4, wmma::mem_row_major);
        wmma::store_matrix_sync(Cs + (wm * 16) * (BN + 4) + wn * 32 + 16, acc1[0], BN + 4, wmma::mem_row_major);
    } else {
        wmma::store_matrix_sync(Cs + (wm * 16) * (BN + 4) + wn * 16, acc0[0], BN + 4, wmma::mem_row_major);
    }
    __syncthreads();

    if (EPI == 0) {
        for (int idx = tid; idx < BM * BN; idx += 128) {
            int m = idx / BN, n = idx % BN;
            Cf[(long)(m0 + m) * N + n0 + n + z * sC] = Cs[m * (BN + 4) + n] + bias[n0 + n];
        }
    } else if (EPI == 2) {
        const int d = (int)z;
        for (int idx = tid; idx < BM * 16; idx += 128) {
            int m = idx >> 4, jj = idx & 15;
            int b = m0 + m, j = (n0 >> 2) + jj;
            float ig = sigm(Cs[m * (BN + 4) + jj * 4 + 0] + bias[n0 + jj * 4 + 0]);
            float fg = sigm(Cs[m * (BN + 4) + jj * 4 + 1] + bias[n0 + jj * 4 + 1]);
            float gg = tanhf(Cs[m * (BN + 4) + jj * 4 + 2] + bias[n0 + jj * 4 + 2]);
            float og = sigm(Cs[m * (BN + 4) + jj * 4 + 3] + bias[n0 + jj * 4 + 3]);
            int ci = (d * NB + b) * NH + j;
            float cn = fg * cst[ci] + ig * gg;
            float hn = og * tanhf(cn);
            cst[ci] = cn;
            __half h = __float2half(hn);
            X2out[(d * NB + b) * KX2 + 544 + j] = h;   // into NEXT X2 buffer
            X1[b * KX1 + d * NH + j] = h;              // into X1 (hh slice)
        }
    } else {  // EPI == 4, BN == 32: combined attn1 + fc
        if (n0 < NT) {
            for (int idx = tid; idx < BM * BN; idx += 128) {
                int m = idx / BN, n = idx % BN;
                float v = tanhf(Cs[m * (BN + 4) + n] + bias[n0 + n]);
                Ch[(long)(m0 + m) * NT + n0 + n] = __float2half(v);
            }
        } else if (tstep >= 0) {
            int r = tid >> 2, g = tid & 3;
            float s = 0.0f;
#pragma unroll
            for (int jj = 0; jj < 8; jj++) {
                int n = g * 8 + jj;
                float v = fmaxf(Cs[r * (BN + 4) + n] + bias[n0 + n], 0.0f);
                s += v * w2[n0 - NT + n];
            }
            red[tid] = s;
            __syncthreads();
            if (tid < 32) {
                float t = red[tid * 4] + red[tid * 4 + 1] + red[tid * 4 + 2] + red[tid * 4 + 3];
                atomicAdd(&out[(m0 + tid) * NFT + tstep], t);
            }
        }
    }
}

constexpr int smem_sz(int bn, int nw) {
    return (ST * BM * SK + ST * nw * bn * SK) * 2 + BM * (bn + 4) * 4 + 128 * 4 + 256;
}
constexpr int SMEM32_2 = smem_sz(32, 2);
constexpr int SMEM32_1 = smem_sz(32, 1);
constexpr int SMEM64_2 = smem_sz(64, 2);

// ---------------- ctx: one block per batch row; softmax once; fp8 enc stream ----------------
__global__ __launch_bounds__(128) void ctx_kernel(
    const float* __restrict__ logits, const float* __restrict__ alpha,
    const unsigned char* __restrict__ enc8, __half* __restrict__ X2h, __half* __restrict__ X1h,
    const float* __restrict__ ffC, const float* __restrict__ ffN)
{
    const int b = blockIdx.x;
    const int tid = threadIdx.x;
    __shared__ float wt[NT];
    __shared__ float sred[4];
    const float* lrow = logits + b * NT;

    float mx = -1e30f;
    for (int t = tid; t < NT; t += 128) mx = fmaxf(mx, lrow[t]);
#pragma unroll
    for (int o = 16; o > 0; o >>= 1) mx = fmaxf(mx, __shfl_xor_sync(0xffffffffu, mx, o));
    if ((tid & 31) == 0) sred[tid >> 5] = mx;
    __syncthreads();
    mx = fmaxf(fmaxf(sred[0], sred[1]), fmaxf(sred[2], sred[3]));
    __syncthreads();

    float s = 0.0f;
    for (int t = tid; t < NT; t += 128) { float e = expf(lrow[t] - mx); wt[t] = e; s += e; }
#pragma unroll
    for (int o = 16; o > 0; o >>= 1) s += __shfl_xor_sync(0xffffffffu, s, o);
    if ((tid & 31) == 0) sred[tid >> 5] = s;
    __syncthreads();
    s = sred[0] + sred[1] + sred[2] + sred[3];
    float inv = 1.0f / s;
    for (int t = tid; t < NT; t += 128) wt[t] *= inv * alpha[b * 24 + t / 24];
    __syncthreads();

    // 4 columns per thread (128 thr x 4 = 512 cols), fp8 packed as uint
    const unsigned* eb = (const unsigned*)(enc8 + (long)b * NT * NE) + tid;
    float a0 = 0, a1 = 0, a2 = 0, a3 = 0;
#pragma unroll 1
    for (int t = 0; t < NT; t += 8) {
        unsigned q0 = eb[(t + 0) * 128];
        unsigned q1 = eb[(t + 1) * 128];
        unsigned q2 = eb[(t + 2) * 128];
        unsigned q3 = eb[(t + 3) * 128];
        unsigned q4 = eb[(t + 4) * 128];
        unsigned q5 = eb[(t + 5) * 128];
        unsigned q6 = eb[(t + 6) * 128];
        unsigned q7 = eb[(t + 7) * 128];
#pragma unroll
        for (int i = 0; i < 8; i++) {
            unsigned q = (i == 0) ? q0 : (i == 1) ? q1 : (i == 2) ? q2 : (i == 3) ? q3
                       : (i == 4) ? q4 : (i == 5) ? q5 : (i == 6) ? q6 : q7;
            float w = wt[t + i];
            float2 f01 = __half22float2(fp8x2_to_half2((unsigned short)(q & 0xffff)));
            float2 f23 = __half22float2(fp8x2_to_half2((unsigned short)(q >> 16)));
            a0 += w * f01.x; a1 += w * f01.y; a2 += w * f23.x; a3 += w * f23.y;
        }
    }
    __half2 p01 = __floats2half2_rn(a0, a1);
    __half2 p23 = __floats2half2_rn(a2, a3);
    long o0 = (long)b * KX2 + 4 * tid;
    long o1 = (long)(NB + b) * KX2 + 4 * tid;
    *(__half2*)(X2h + o0) = p01; *(__half2*)(X2h + o0 + 2) = p23;
    *(__half2*)(X2h + o1) = p01; *(__half2*)(X2h + o1 + 2) = p23;

    if (tid < NM) {
        __half h = __float2half(ffC[b * NFT * NM + tid]);
        X2h[(long)b * KX2 + 512 + tid] = h;
        X2h[(long)(NB + b) * KX2 + 512 + tid] = h;
        if (ffN != nullptr)
            X1h[b * KX1 + 512 + tid] = __float2half(ffN[b * NFT * NM + tid]);
    }
}

// ---------------- launch ----------------
extern "C" void kernel_launch(void* const* d_in, const int* in_sizes, int n_in,
                              void* d_out, int out_size)
{
    const float* enc    = (const float*)d_in[0];
    const float* fhist  = (const float*)d_in[1];
    const float* ffut   = (const float*)d_in[3];
    const float* hidden = (const float*)d_in[4];
    const float* cell   = (const float*)d_in[5];
    const float* aW1    = (const float*)d_in[6];
    const float* ab1    = (const float*)d_in[7];
    const float* aW2    = (const float*)d_in[8];
    const float* ab2    = (const float*)d_in[9];
    const float* Wih    = (const float*)d_in[10];
    const float* Whh    = (const float*)d_in[11];
    const float* bih    = (const float*)d_in[12];
    const float* bhh    = (const float*)d_in[13];
    const float* fW1    = (const float*)d_in[14];
    const float* fb1    = (const float*)d_in[15];
    const float* fW2    = (const float*)d_in[16];
    const float* fb2    = (const float*)d_in[17];
    float* out = (float*)d_out;

    __half *pX1, *pTmp, *pX2, *pAW2, *pWcat, *pWcomb;
    unsigned char* pEnc8;
    float *pLog, *pAlpha, *pC, *pBias2, *pBcomb;
    cudaGetSymbolAddress((void**)&pX1, g_X1h);
    cudaGetSymbolAddress((void**)&pTmp, g_tmph);
    cudaGetSymbolAddress((void**)&pX2, g_X2h);
    cudaGetSymbolAddress((void**)&pAW2, g_aW2h);
    cudaGetSymbolAddress((void**)&pWcat, g_Wcath);
    cudaGetSymbolAddress((void**)&pWcomb, g_Wcombh);
    cudaGetSymbolAddress((void**)&pEnc8, g_enc8);
    cudaGetSymbolAddress((void**)&pLog, g_logits);
    cudaGetSymbolAddress((void**)&pAlpha, g_alpha);
    cudaGetSymbolAddress((void**)&pC, g_c);
    cudaGetSymbolAddress((void**)&pBias2, g_bias2);
    cudaGetSymbolAddress((void**)&pBcomb, g_bcomb);

    cudaFuncSetAttribute(hgemm2<32, 0, 1>, cudaFuncAttributeMaxDynamicSharedMemorySize, SMEM32_1);
    cudaFuncSetAttribute(hgemm2<32, 4, 2>, cudaFuncAttributeMaxDynamicSharedMemorySize, SMEM32_2);
    cudaFuncSetAttribute(hgemm2<64, 2, 2>, cudaFuncAttributeMaxDynamicSharedMemorySize, SMEM64_2);

    setup_kernel<<<512, 256>>>(hidden, cell, ffut, fb2, out, pC, pX1, pX2);
    alpha_kernel<<<NB, 576>>>(ffut, fhist, pAlpha);
    wcat_kernel<<<4096, 256>>>(Wih, Whh, bih, bhh, pWcat, pBias2);
    wcomb_kernel<<<1024, 256>>>(aW1, ab1, fW1, fb1, pWcomb, pBcomb);
    conv_half<<<1024, 256>>>(aW2, pAW2, NT * NT);
    conv_fp8<<<4096, 256>>>((const float4*)enc, (unsigned*)pEnc8, (int)((long)NB * NT * NE / 4));

    for (int t = 0; t < NFT; t++) {
        __half* X2cur = pX2 + (t & 1) * sX2B;
        __half* X2nxt = pX2 + ((t + 1) & 1) * sX2B;

        // combined: tmp = tanh(X1 @ aW1^T + ab1); fc for step t-1 (skipped at t=0)
        hgemm2<32, 4, 2><<<dim3(NB / BM, NC / 32, 1), 128, SMEM32_2>>>(
            pX1, pWcomb, pWcomb + oWcomb, pBcomb, KX1, NT, 0, 0, 0,
            nullptr, 0, pTmp,
            nullptr, nullptr, nullptr, fW2, out, t - 1, 0);
        // attn2: logits = tmp @ aW2^T + ab2 (fp32, plain fp16 weights, 1 mma term)
        hgemm2<32, 0, 1><<<dim3(NB / BM, NT / 32, 1), 128, SMEM32_1>>>(
            pTmp, pAW2, pAW2, ab2, NT, NT, 0, 0, 0,
            pLog, 0, nullptr,
            nullptr, nullptr, nullptr, nullptr, nullptr, 0, 0);
        // ctx -> X2cur; scatters ff[t] into X2cur, ff[t+1] into X1
        const float* ffN = (t + 1 < NFT) ? (ffut + (t + 1) * NM) : nullptr;
        ctx_kernel<<<NB, 128>>>(pLog, pAlpha, pEnc8, X2cur, pX1,
                                ffut + t * NM, ffN);
        // gates GEMM + fused LSTM cell; h -> X1 / X2nxt, c updated
        hgemm2<64, 2, 2><<<dim3(NB / BM, G4 / 64, 2), 128, SMEM64_2>>>(
            X2cur, pWcat, pWcat + oWcat, pBias2, KX2, G4,
            (long)NB * KX2, (long)G4 * KX2, (long)G4,
            nullptr, 0, nullptr,
            pC, pX1, X2nxt, nullptr, nullptr, 0, 0);
    }
    // tail: fc for the last step (t = 23), fc columns only
    hgemm2<32, 4, 2><<<dim3(NB / BM, NH / 32, 1), 128, SMEM32_2>>>(
        pX1, pWcomb, pWcomb + oWcomb, pBcomb, KX1, NT, 0, 0, 0,
        nullptr, 0, pTmp,
        nullptr, nullptr, nullptr, fW2, out, NFT - 1, NT / 32);
    (void)in_sizes; (void)n_in; (void)out_size;
}